// round 8
// baseline (speedup 1.0000x reference)
#include <cuda_runtime.h>
#include <cuda_fp16.h>
#include <cstdint>

// ---------------------------------------------------------------------------
// GAT 3-layer forward, gather-based (CSR by dst).
// R8: node gather = one warp per node with edge list split across lane groups
// (2 groups for H=2, 4 for H=1) + shfl combine -> 2-4x edge MLP per warp.
// TC GEMM (hi/lo fp16 split), fused score epilogue, CSR overlapped w/ GEMM0.
// ---------------------------------------------------------------------------

#define MAXN 50000
#define MAXE 800000
#define MAXW 128

__device__ __half g_feat_h[MAXN * MAXW];
__device__ float  g_hid [MAXN * MAXW];
__device__ float  g_t   [MAXN * 2];
__device__ int g_cnt[MAXN + 1];
__device__ int g_ptr[MAXN + 1];
__device__ int g_cur[MAXN + 1];
__device__ int g_csr[MAXE];

__device__ __forceinline__ void mma16816(float* d, const uint32_t* a, const uint32_t* b) {
    asm volatile(
        "mma.sync.aligned.m16n8k16.row.col.f32.f16.f16.f32 "
        "{%0,%1,%2,%3}, {%4,%5,%6,%7}, {%8,%9}, {%0,%1,%2,%3};\n"
        : "+f"(d[0]), "+f"(d[1]), "+f"(d[2]), "+f"(d[3])
        : "r"(a[0]), "r"(a[1]), "r"(a[2]), "r"(a[3]), "r"(b[0]), "r"(b[1]));
}

// ---------------- tensor-core GEMM + fused score epilogue ----------------
template <int BN, int H>
__global__ void __launch_bounds__(256, 1)
gemm_tc_kernel(const float* __restrict__ A,
               const float* __restrict__ W,
               const float* __restrict__ attn,
               __half* __restrict__ C_h,
               float* __restrict__ t, int N) {
    constexpr int BM = 128, K = 128;
    constexpr int SK = K + 8;
    constexpr int WN = BN / 4;
    constexpr int MT = 4;
    constexpr int NT = WN / 8;
    constexpr int F  = BN / H;

    extern __shared__ __half sm[];
    __half* sAhi = sm;
    __half* sAlo = sAhi + BM * SK;
    __half* sWhi = sAlo + BM * SK;
    __half* sWlo = sWhi + BN * SK;
    float*  sm_el = (float*)(sWlo + BN * SK);

    const int tid  = threadIdx.x;
    const int warp = tid >> 5;
    const int lane = tid & 31;
    const int row0 = blockIdx.x * BM;
    const int m0w  = (warp >> 2) * 64;
    const int n0w  = (warp & 3) * WN;
    const int fr   = lane >> 2;
    const int fc   = lane & 3;

    for (int i = tid; i < BM * H; i += 256) sm_el[i] = 0.f;

    const float4* A4 = (const float4*)A;
    for (int f = tid; f < BM * 32; f += 256) {
        int r = f >> 5, c4 = f & 31;
        float4 v = make_float4(0.f, 0.f, 0.f, 0.f);
        if (row0 + r < N) v = A4[(size_t)(row0 + r) * 32 + c4];
        float vv[4] = {v.x, v.y, v.z, v.w};
        __half hi[4], lo[4];
#pragma unroll
        for (int j = 0; j < 4; j++) {
            hi[j] = __float2half(vv[j]);
            lo[j] = __float2half(vv[j] - __half2float(hi[j]));
        }
        int off = r * SK + c4 * 4;
        *(uint2*)&sAhi[off] = *(uint2*)hi;
        *(uint2*)&sAlo[off] = *(uint2*)lo;
    }
    const float4* W4 = (const float4*)W;
    for (int f = tid; f < BN * 32; f += 256) {
        int n = f >> 5, c4 = f & 31;
        float4 v = W4[(size_t)n * 32 + c4];
        float vv[4] = {v.x, v.y, v.z, v.w};
        __half hi[4], lo[4];
#pragma unroll
        for (int j = 0; j < 4; j++) {
            hi[j] = __float2half(vv[j]);
            lo[j] = __float2half(vv[j] - __half2float(hi[j]));
        }
        int off = n * SK + c4 * 4;
        *(uint2*)&sWhi[off] = *(uint2*)hi;
        *(uint2*)&sWlo[off] = *(uint2*)lo;
    }
    __syncthreads();

    float acc[MT][NT][4];
#pragma unroll
    for (int mt = 0; mt < MT; mt++)
#pragma unroll
        for (int nt = 0; nt < NT; nt++)
#pragma unroll
            for (int j = 0; j < 4; j++) acc[mt][nt][j] = 0.f;

#pragma unroll
    for (int kt = 0; kt < 8; kt++) {
        const int k0 = kt * 16;
        uint32_t ahi[MT][4], alo[MT][4];
#pragma unroll
        for (int mt = 0; mt < MT; mt++) {
            const __half* pa = &sAhi[(m0w + mt * 16 + fr) * SK + k0 + fc * 2];
            const __half* pl = &sAlo[(m0w + mt * 16 + fr) * SK + k0 + fc * 2];
            ahi[mt][0] = *(const uint32_t*)pa;
            ahi[mt][1] = *(const uint32_t*)(pa + 8 * SK);
            ahi[mt][2] = *(const uint32_t*)(pa + 8);
            ahi[mt][3] = *(const uint32_t*)(pa + 8 * SK + 8);
            alo[mt][0] = *(const uint32_t*)pl;
            alo[mt][1] = *(const uint32_t*)(pl + 8 * SK);
            alo[mt][2] = *(const uint32_t*)(pl + 8);
            alo[mt][3] = *(const uint32_t*)(pl + 8 * SK + 8);
        }
        uint32_t bhi[NT][2], blo[NT][2];
#pragma unroll
        for (int nt = 0; nt < NT; nt++) {
            const __half* pb = &sWhi[(n0w + nt * 8 + fr) * SK + k0 + fc * 2];
            const __half* pl = &sWlo[(n0w + nt * 8 + fr) * SK + k0 + fc * 2];
            bhi[nt][0] = *(const uint32_t*)pb;
            bhi[nt][1] = *(const uint32_t*)(pb + 8);
            blo[nt][0] = *(const uint32_t*)pl;
            blo[nt][1] = *(const uint32_t*)(pl + 8);
        }
#pragma unroll
        for (int mt = 0; mt < MT; mt++)
#pragma unroll
            for (int nt = 0; nt < NT; nt++) {
                mma16816(acc[mt][nt], ahi[mt], bhi[nt]);
                mma16816(acc[mt][nt], ahi[mt], blo[nt]);
                mma16816(acc[mt][nt], alo[mt], bhi[nt]);
            }
    }

    const int hh = n0w / F;
    float av0[NT], av1[NT];
#pragma unroll
    for (int nt = 0; nt < NT; nt++) {
        int col = n0w + nt * 8 + fc * 2;
        av0[nt] = attn[col];
        av1[nt] = attn[col + 1];
    }
#pragma unroll
    for (int mt = 0; mt < MT; mt++) {
        int rb0 = m0w + mt * 16 + fr;
        int rb1 = rb0 + 8;
        float p0 = 0.f, p1 = 0.f;
#pragma unroll
        for (int nt = 0; nt < NT; nt++) {
            p0 += acc[mt][nt][0] * av0[nt] + acc[mt][nt][1] * av1[nt];
            p1 += acc[mt][nt][2] * av0[nt] + acc[mt][nt][3] * av1[nt];
        }
        atomicAdd(&sm_el[rb0 * H + hh], p0);
        atomicAdd(&sm_el[rb1 * H + hh], p1);
        int g0 = row0 + rb0, g1 = row0 + rb1;
        if (g0 < N) {
#pragma unroll
            for (int nt = 0; nt < NT; nt++) {
                int col = n0w + nt * 8 + fc * 2;
                __half2 hv = __halves2half2(__float2half(acc[mt][nt][0]),
                                            __float2half(acc[mt][nt][1]));
                *(__half2*)&C_h[(size_t)g0 * BN + col] = hv;
            }
        }
        if (g1 < N) {
#pragma unroll
            for (int nt = 0; nt < NT; nt++) {
                int col = n0w + nt * 8 + fc * 2;
                __half2 hv = __halves2half2(__float2half(acc[mt][nt][2]),
                                            __float2half(acc[mt][nt][3]));
                *(__half2*)&C_h[(size_t)g1 * BN + col] = hv;
            }
        }
    }
    __syncthreads();
    for (int i = tid; i < BM * H; i += 256) {
        int r = i / H, h2 = i % H;
        int row = row0 + r;
        if (row < N) {
            float el = sm_el[i];
            float sv = el > 0.f ? el : 0.2f * el;
            t[(size_t)row * H + h2] = __expf(sv);
        }
    }
}

// ---------------- CSR build ----------------
__global__ void zero_cnt_kernel(int* __restrict__ cnt, int n) {
    int i = blockIdx.x * blockDim.x + threadIdx.x;
    if (i < n) cnt[i] = 0;
}

__global__ void hist_kernel(const int* __restrict__ dst, int* __restrict__ cnt, int E) {
    int i = (blockIdx.x * blockDim.x + threadIdx.x) * 4;
    if (i + 4 <= E) {
        int4 d = *(const int4*)&dst[i];
        atomicAdd(&cnt[d.x], 1);
        atomicAdd(&cnt[d.y], 1);
        atomicAdd(&cnt[d.z], 1);
        atomicAdd(&cnt[d.w], 1);
    } else {
        for (; i < E; i++) atomicAdd(&cnt[dst[i]], 1);
    }
}

__global__ void scan_kernel(const int* __restrict__ cnt, int* __restrict__ ptr,
                            int* __restrict__ cur, int N) {
    __shared__ int part[1024];
    const int tid = threadIdx.x;
    const int chunk = (N + 1023) / 1024;
    const int b = tid * chunk;
    int s = 0;
    for (int i = 0; i < chunk; i++)
        if (b + i < N) s += cnt[b + i];
    part[tid] = s;
    __syncthreads();
    for (int off = 1; off < 1024; off <<= 1) {
        int v = (tid >= off) ? part[tid - off] : 0;
        __syncthreads();
        part[tid] += v;
        __syncthreads();
    }
    int run = (tid > 0) ? part[tid - 1] : 0;
    for (int i = 0; i < chunk; i++) {
        if (b + i < N) {
            ptr[b + i] = run;
            cur[b + i] = run;
            run += cnt[b + i];
        }
    }
    if (tid == 1023) ptr[N] = part[1023];
}

__global__ void scatter_kernel(const int* __restrict__ src, const int* __restrict__ dst,
                               int* __restrict__ cur, int* __restrict__ csr, int E) {
    int i = (blockIdx.x * blockDim.x + threadIdx.x) * 4;
    if (i + 4 <= E) {
        int4 d = *(const int4*)&dst[i];
        int4 u = *(const int4*)&src[i];
        int p0 = atomicAdd(&cur[d.x], 1);
        int p1 = atomicAdd(&cur[d.y], 1);
        int p2 = atomicAdd(&cur[d.z], 1);
        int p3 = atomicAdd(&cur[d.w], 1);
        csr[p0] = u.x; csr[p1] = u.y; csr[p2] = u.z; csr[p3] = u.w;
    } else {
        for (; i < E; i++) {
            int p = atomicAdd(&cur[dst[i]], 1);
            csr[p] = src[i];
        }
    }
}

// ---------------- node gather: one warp per node, GROUPS lane-groups -------
// GROUPS lane groups each process a contiguous slice of the edge list over
// the full feature row (LPR lanes x 16B), then shfl-combine.
template <int H, int F, bool RELU>
__global__ void node_kernel(const int* __restrict__ ptr,
                            const int* __restrict__ csr,
                            const __half* __restrict__ feath,
                            const float* __restrict__ t,
                            const float* __restrict__ bias,
                            float* __restrict__ out, int N) {
    constexpr int LPR    = H * F / 8;        // lanes per feature row: 16 / 8
    constexpr int GROUPS = 32 / LPR;         // 2 (H=2) / 4 (H=1)
    const int gid  = blockIdx.x * blockDim.x + threadIdx.x;
    const int node = gid >> 5;
    const int lane = threadIdx.x & 31;
    if (node >= N) return;
    const int g   = lane / LPR;
    const int sub = lane % LPR;
    const int h   = (H == 2) ? (sub >> 3) : 0;

    const int beg = ptr[node];
    const int len = ptr[node + 1] - beg;
    // contiguous slice for this group
    const int q = len / GROUPS, r = len % GROUPS;
    const int myLen = q + (g < r ? 1 : 0);
    const int myBeg = beg + g * q + (g < r ? g : r);
    const int myEnd = myBeg + myLen;

    const uint4* feat8 = (const uint4*)feath;

    float acc[8];
#pragma unroll
    for (int k = 0; k < 8; k++) acc[k] = 0.f;
    float d = 0.f;

    int i = myBeg;
    for (; i + 4 <= myEnd; i += 4) {
        int u0 = __ldg(&csr[i + 0]);
        int u1 = __ldg(&csr[i + 1]);
        int u2 = __ldg(&csr[i + 2]);
        int u3 = __ldg(&csr[i + 3]);
        float t0 = __ldg(&t[(size_t)u0 * H + h]);
        float t1 = __ldg(&t[(size_t)u1 * H + h]);
        float t2 = __ldg(&t[(size_t)u2 * H + h]);
        float t3 = __ldg(&t[(size_t)u3 * H + h]);
        uint4 v0 = feat8[(size_t)u0 * LPR + sub];
        uint4 v1 = feat8[(size_t)u1 * LPR + sub];
        uint4 v2 = feat8[(size_t)u2 * LPR + sub];
        uint4 v3 = feat8[(size_t)u3 * LPR + sub];
        d += (t0 + t1) + (t2 + t3);
        const __half2* p0 = (const __half2*)&v0;
        const __half2* p1 = (const __half2*)&v1;
        const __half2* p2 = (const __half2*)&v2;
        const __half2* p3 = (const __half2*)&v3;
#pragma unroll
        for (int k = 0; k < 4; k++) {
            float2 f0 = __half22float2(p0[k]);
            float2 f1 = __half22float2(p1[k]);
            float2 f2 = __half22float2(p2[k]);
            float2 f3 = __half22float2(p3[k]);
            acc[2*k]   = fmaf(t0, f0.x, acc[2*k]);
            acc[2*k+1] = fmaf(t0, f0.y, acc[2*k+1]);
            acc[2*k]   = fmaf(t1, f1.x, acc[2*k]);
            acc[2*k+1] = fmaf(t1, f1.y, acc[2*k+1]);
            acc[2*k]   = fmaf(t2, f2.x, acc[2*k]);
            acc[2*k+1] = fmaf(t2, f2.y, acc[2*k+1]);
            acc[2*k]   = fmaf(t3, f3.x, acc[2*k]);
            acc[2*k+1] = fmaf(t3, f3.y, acc[2*k+1]);
        }
    }
    for (; i < myEnd; i++) {
        int u = __ldg(&csr[i]);
        float tv = __ldg(&t[(size_t)u * H + h]);
        uint4 v = feat8[(size_t)u * LPR + sub];
        const __half2* p = (const __half2*)&v;
        d += tv;
#pragma unroll
        for (int k = 0; k < 4; k++) {
            float2 f = __half22float2(p[k]);
            acc[2*k]   = fmaf(tv, f.x, acc[2*k]);
            acc[2*k+1] = fmaf(tv, f.y, acc[2*k+1]);
        }
    }

    // combine lane groups (identical h-pattern per group => lane-correct)
    __syncwarp();
#pragma unroll
    for (int off = 16; off >= LPR; off >>= 1) {
#pragma unroll
        for (int k = 0; k < 8; k++)
            acc[k] += __shfl_xor_sync(0xffffffffu, acc[k], off);
        d += __shfl_xor_sync(0xffffffffu, d, off);
    }
    if (g != 0) return;

    float inv = d > 0.f ? __frcp_rn(d) : 0.f;
    float4 b0 = ((const float4*)bias)[sub * 2 + 0];
    float4 b1 = ((const float4*)bias)[sub * 2 + 1];
    float4 o0, o1;
    o0.x = fmaf(acc[0], inv, b0.x); o0.y = fmaf(acc[1], inv, b0.y);
    o0.z = fmaf(acc[2], inv, b0.z); o0.w = fmaf(acc[3], inv, b0.w);
    o1.x = fmaf(acc[4], inv, b1.x); o1.y = fmaf(acc[5], inv, b1.y);
    o1.z = fmaf(acc[6], inv, b1.z); o1.w = fmaf(acc[7], inv, b1.w);
    if (RELU) {
        o0.x = fmaxf(o0.x, 0.f); o0.y = fmaxf(o0.y, 0.f);
        o0.z = fmaxf(o0.z, 0.f); o0.w = fmaxf(o0.w, 0.f);
        o1.x = fmaxf(o1.x, 0.f); o1.y = fmaxf(o1.y, 0.f);
        o1.z = fmaxf(o1.z, 0.f); o1.w = fmaxf(o1.w, 0.f);
    }
    ((float4*)out)[(size_t)node * LPR * 2 + sub * 2 + 0] = o0;
    ((float4*)out)[(size_t)node * LPR * 2 + sub * 2 + 1] = o1;
}

// ---------------------------------------------------------------------------
static cudaStream_t s_side = nullptr;
static cudaEvent_t  ev_fork = nullptr, ev_join = nullptr;

extern "C" void kernel_launch(void* const* d_in, const int* in_sizes, int n_in,
                              void* d_out, int out_size) {
    const float* feat    = (const float*)d_in[0];
    const float* W0      = (const float*)d_in[1];
    const float* attn_l0 = (const float*)d_in[2];
    const float* bias0   = (const float*)d_in[3];
    const float* W1      = (const float*)d_in[4];
    const float* attn_l1 = (const float*)d_in[5];
    const float* bias1   = (const float*)d_in[6];
    const float* W2      = (const float*)d_in[7];
    const float* attn_l2 = (const float*)d_in[8];
    const float* bias2   = (const float*)d_in[9];
    const int*   src     = (const int*)d_in[10];
    const int*   dst     = (const int*)d_in[11];

    const int N = in_sizes[0] / 128;
    const int E = in_sizes[10];

    __half* p_feath;
    float *p_hid, *p_t;
    int *p_cnt, *p_ptr, *p_cur, *p_csr;
    cudaGetSymbolAddress((void**)&p_feath, g_feat_h);
    cudaGetSymbolAddress((void**)&p_hid,   g_hid);
    cudaGetSymbolAddress((void**)&p_t,     g_t);
    cudaGetSymbolAddress((void**)&p_cnt,   g_cnt);
    cudaGetSymbolAddress((void**)&p_ptr,   g_ptr);
    cudaGetSymbolAddress((void**)&p_cur,   g_cur);
    cudaGetSymbolAddress((void**)&p_csr,   g_csr);

    if (s_side == nullptr) {
        cudaStreamCreateWithFlags(&s_side, cudaStreamNonBlocking);
        cudaEventCreateWithFlags(&ev_fork, cudaEventDisableTiming);
        cudaEventCreateWithFlags(&ev_join, cudaEventDisableTiming);
    }

    constexpr int SK = 128 + 8;
    const int SMEM128 = (2 * 128 + 2 * 128) * SK * 2 + 128 * 2 * 4;
    const int SMEM64  = (2 * 128 + 2 * 64)  * SK * 2 + 128 * 1 * 4;
    cudaFuncSetAttribute(gemm_tc_kernel<128, 2>,
                         cudaFuncAttributeMaxDynamicSharedMemorySize, SMEM128);
    cudaFuncSetAttribute(gemm_tc_kernel<64, 1>,
                         cudaFuncAttributeMaxDynamicSharedMemorySize, SMEM64);

    const int gGemm  = (N + 127) / 128;
    const int gEdge4 = (E / 4 + 255) / 256 + 1;
    const int gNode  = (N * 32 + 255) / 256;

    // -------- fork: CSR build on side stream, GEMM0 on main --------
    cudaEventRecord(ev_fork, 0);
    cudaStreamWaitEvent(s_side, ev_fork, 0);

    zero_cnt_kernel<<<(N + 1 + 255) / 256, 256, 0, s_side>>>(p_cnt, N + 1);
    hist_kernel<<<gEdge4, 256, 0, s_side>>>(dst, p_cnt, E);
    scan_kernel<<<1, 1024, 0, s_side>>>(p_cnt, p_ptr, p_cur, N);
    scatter_kernel<<<gEdge4, 256, 0, s_side>>>(src, dst, p_cur, p_csr, E);
    cudaEventRecord(ev_join, s_side);

    gemm_tc_kernel<128, 2><<<gGemm, 256, SMEM128>>>(feat, W0, attn_l0, p_feath, p_t, N);

    cudaStreamWaitEvent(0, ev_join, 0);

    node_kernel<2, 64, true><<<gNode, 256>>>(p_ptr, p_csr, p_feath, p_t, bias0, p_hid, N);

    gemm_tc_kernel<128, 2><<<gGemm, 256, SMEM128>>>(p_hid, W1, attn_l1, p_feath, p_t, N);
    node_kernel<2, 64, true><<<gNode, 256>>>(p_ptr, p_csr, p_feath, p_t, bias1, p_hid, N);

    gemm_tc_kernel<64, 1><<<gGemm, 256, SMEM64>>>(p_hid, W2, attn_l2, p_feath, p_t, N);
    node_kernel<1, 64, false><<<gNode, 256>>>(p_ptr, p_csr, p_feath, p_t, bias2, (float*)d_out, N);
}

// round 9
// speedup vs baseline: 1.0372x; 1.0372x over previous
#include <cuda_runtime.h>
#include <cuda_fp16.h>
#include <cstdint>

// ---------------------------------------------------------------------------
// GAT 3-layer forward, gather-based (CSR by dst).
// R9: revert node gather to R7 (2 nodes/warp, unroll-4); reorder launches so
// ncu's fixed profile slot captures the TC GEMM instead of scatter.
// TC GEMM (hi/lo fp16 split, 3 mma passes), fused score epilogue,
// CSR build overlapped with GEMM0 via side stream.
// ---------------------------------------------------------------------------

#define MAXN 50000
#define MAXE 800000
#define MAXW 128

__device__ __half g_feat_h[MAXN * MAXW];
__device__ float  g_hid [MAXN * MAXW];
__device__ float  g_t   [MAXN * 2];
__device__ int g_cnt[MAXN + 1];
__device__ int g_ptr[MAXN + 1];
__device__ int g_cur[MAXN + 1];
__device__ int g_csr[MAXE];

__device__ __forceinline__ void mma16816(float* d, const uint32_t* a, const uint32_t* b) {
    asm volatile(
        "mma.sync.aligned.m16n8k16.row.col.f32.f16.f16.f32 "
        "{%0,%1,%2,%3}, {%4,%5,%6,%7}, {%8,%9}, {%0,%1,%2,%3};\n"
        : "+f"(d[0]), "+f"(d[1]), "+f"(d[2]), "+f"(d[3])
        : "r"(a[0]), "r"(a[1]), "r"(a[2]), "r"(a[3]), "r"(b[0]), "r"(b[1]));
}

// ---------------- tensor-core GEMM + fused score epilogue ----------------
template <int BN, int H>
__global__ void __launch_bounds__(256, 1)
gemm_tc_kernel(const float* __restrict__ A,
               const float* __restrict__ W,
               const float* __restrict__ attn,
               __half* __restrict__ C_h,
               float* __restrict__ t, int N) {
    constexpr int BM = 128, K = 128;
    constexpr int SK = K + 8;
    constexpr int WN = BN / 4;
    constexpr int MT = 4;
    constexpr int NT = WN / 8;
    constexpr int F  = BN / H;

    extern __shared__ __half sm[];
    __half* sAhi = sm;
    __half* sAlo = sAhi + BM * SK;
    __half* sWhi = sAlo + BM * SK;
    __half* sWlo = sWhi + BN * SK;
    float*  sm_el = (float*)(sWlo + BN * SK);

    const int tid  = threadIdx.x;
    const int warp = tid >> 5;
    const int lane = tid & 31;
    const int row0 = blockIdx.x * BM;
    const int m0w  = (warp >> 2) * 64;
    const int n0w  = (warp & 3) * WN;
    const int fr   = lane >> 2;
    const int fc   = lane & 3;

    for (int i = tid; i < BM * H; i += 256) sm_el[i] = 0.f;

    const float4* A4 = (const float4*)A;
    for (int f = tid; f < BM * 32; f += 256) {
        int r = f >> 5, c4 = f & 31;
        float4 v = make_float4(0.f, 0.f, 0.f, 0.f);
        if (row0 + r < N) v = A4[(size_t)(row0 + r) * 32 + c4];
        float vv[4] = {v.x, v.y, v.z, v.w};
        __half hi[4], lo[4];
#pragma unroll
        for (int j = 0; j < 4; j++) {
            hi[j] = __float2half(vv[j]);
            lo[j] = __float2half(vv[j] - __half2float(hi[j]));
        }
        int off = r * SK + c4 * 4;
        *(uint2*)&sAhi[off] = *(uint2*)hi;
        *(uint2*)&sAlo[off] = *(uint2*)lo;
    }
    const float4* W4 = (const float4*)W;
    for (int f = tid; f < BN * 32; f += 256) {
        int n = f >> 5, c4 = f & 31;
        float4 v = W4[(size_t)n * 32 + c4];
        float vv[4] = {v.x, v.y, v.z, v.w};
        __half hi[4], lo[4];
#pragma unroll
        for (int j = 0; j < 4; j++) {
            hi[j] = __float2half(vv[j]);
            lo[j] = __float2half(vv[j] - __half2float(hi[j]));
        }
        int off = n * SK + c4 * 4;
        *(uint2*)&sWhi[off] = *(uint2*)hi;
        *(uint2*)&sWlo[off] = *(uint2*)lo;
    }
    __syncthreads();

    float acc[MT][NT][4];
#pragma unroll
    for (int mt = 0; mt < MT; mt++)
#pragma unroll
        for (int nt = 0; nt < NT; nt++)
#pragma unroll
            for (int j = 0; j < 4; j++) acc[mt][nt][j] = 0.f;

#pragma unroll
    for (int kt = 0; kt < 8; kt++) {
        const int k0 = kt * 16;
        uint32_t ahi[MT][4], alo[MT][4];
#pragma unroll
        for (int mt = 0; mt < MT; mt++) {
            const __half* pa = &sAhi[(m0w + mt * 16 + fr) * SK + k0 + fc * 2];
            const __half* pl = &sAlo[(m0w + mt * 16 + fr) * SK + k0 + fc * 2];
            ahi[mt][0] = *(const uint32_t*)pa;
            ahi[mt][1] = *(const uint32_t*)(pa + 8 * SK);
            ahi[mt][2] = *(const uint32_t*)(pa + 8);
            ahi[mt][3] = *(const uint32_t*)(pa + 8 * SK + 8);
            alo[mt][0] = *(const uint32_t*)pl;
            alo[mt][1] = *(const uint32_t*)(pl + 8 * SK);
            alo[mt][2] = *(const uint32_t*)(pl + 8);
            alo[mt][3] = *(const uint32_t*)(pl + 8 * SK + 8);
        }
        uint32_t bhi[NT][2], blo[NT][2];
#pragma unroll
        for (int nt = 0; nt < NT; nt++) {
            const __half* pb = &sWhi[(n0w + nt * 8 + fr) * SK + k0 + fc * 2];
            const __half* pl = &sWlo[(n0w + nt * 8 + fr) * SK + k0 + fc * 2];
            bhi[nt][0] = *(const uint32_t*)pb;
            bhi[nt][1] = *(const uint32_t*)(pb + 8);
            blo[nt][0] = *(const uint32_t*)pl;
            blo[nt][1] = *(const uint32_t*)(pl + 8);
        }
#pragma unroll
        for (int mt = 0; mt < MT; mt++)
#pragma unroll
            for (int nt = 0; nt < NT; nt++) {
                mma16816(acc[mt][nt], ahi[mt], bhi[nt]);
                mma16816(acc[mt][nt], ahi[mt], blo[nt]);
                mma16816(acc[mt][nt], alo[mt], bhi[nt]);
            }
    }

    const int hh = n0w / F;
    float av0[NT], av1[NT];
#pragma unroll
    for (int nt = 0; nt < NT; nt++) {
        int col = n0w + nt * 8 + fc * 2;
        av0[nt] = attn[col];
        av1[nt] = attn[col + 1];
    }
#pragma unroll
    for (int mt = 0; mt < MT; mt++) {
        int rb0 = m0w + mt * 16 + fr;
        int rb1 = rb0 + 8;
        float p0 = 0.f, p1 = 0.f;
#pragma unroll
        for (int nt = 0; nt < NT; nt++) {
            p0 += acc[mt][nt][0] * av0[nt] + acc[mt][nt][1] * av1[nt];
            p1 += acc[mt][nt][2] * av0[nt] + acc[mt][nt][3] * av1[nt];
        }
        atomicAdd(&sm_el[rb0 * H + hh], p0);
        atomicAdd(&sm_el[rb1 * H + hh], p1);
        int g0 = row0 + rb0, g1 = row0 + rb1;
        if (g0 < N) {
#pragma unroll
            for (int nt = 0; nt < NT; nt++) {
                int col = n0w + nt * 8 + fc * 2;
                __half2 hv = __halves2half2(__float2half(acc[mt][nt][0]),
                                            __float2half(acc[mt][nt][1]));
                *(__half2*)&C_h[(size_t)g0 * BN + col] = hv;
            }
        }
        if (g1 < N) {
#pragma unroll
            for (int nt = 0; nt < NT; nt++) {
                int col = n0w + nt * 8 + fc * 2;
                __half2 hv = __halves2half2(__float2half(acc[mt][nt][2]),
                                            __float2half(acc[mt][nt][3]));
                *(__half2*)&C_h[(size_t)g1 * BN + col] = hv;
            }
        }
    }
    __syncthreads();
    for (int i = tid; i < BM * H; i += 256) {
        int r = i / H, h2 = i % H;
        int row = row0 + r;
        if (row < N) {
            float el = sm_el[i];
            float sv = el > 0.f ? el : 0.2f * el;
            t[(size_t)row * H + h2] = __expf(sv);
        }
    }
}

// ---------------- CSR build ----------------
__global__ void zero_cnt_kernel(int* __restrict__ cnt, int n) {
    int i = blockIdx.x * blockDim.x + threadIdx.x;
    if (i < n) cnt[i] = 0;
}

__global__ void hist_kernel(const int* __restrict__ dst, int* __restrict__ cnt, int E) {
    int i = (blockIdx.x * blockDim.x + threadIdx.x) * 4;
    if (i + 4 <= E) {
        int4 d = *(const int4*)&dst[i];
        atomicAdd(&cnt[d.x], 1);
        atomicAdd(&cnt[d.y], 1);
        atomicAdd(&cnt[d.z], 1);
        atomicAdd(&cnt[d.w], 1);
    } else {
        for (; i < E; i++) atomicAdd(&cnt[dst[i]], 1);
    }
}

__global__ void scan_kernel(const int* __restrict__ cnt, int* __restrict__ ptr,
                            int* __restrict__ cur, int N) {
    __shared__ int part[1024];
    const int tid = threadIdx.x;
    const int chunk = (N + 1023) / 1024;
    const int b = tid * chunk;
    int s = 0;
    for (int i = 0; i < chunk; i++)
        if (b + i < N) s += cnt[b + i];
    part[tid] = s;
    __syncthreads();
    for (int off = 1; off < 1024; off <<= 1) {
        int v = (tid >= off) ? part[tid - off] : 0;
        __syncthreads();
        part[tid] += v;
        __syncthreads();
    }
    int run = (tid > 0) ? part[tid - 1] : 0;
    for (int i = 0; i < chunk; i++) {
        if (b + i < N) {
            ptr[b + i] = run;
            cur[b + i] = run;
            run += cnt[b + i];
        }
    }
    if (tid == 1023) ptr[N] = part[1023];
}

__global__ void scatter_kernel(const int* __restrict__ src, const int* __restrict__ dst,
                               int* __restrict__ cur, int* __restrict__ csr, int E) {
    int i = (blockIdx.x * blockDim.x + threadIdx.x) * 4;
    if (i + 4 <= E) {
        int4 d = *(const int4*)&dst[i];
        int4 u = *(const int4*)&src[i];
        int p0 = atomicAdd(&cur[d.x], 1);
        int p1 = atomicAdd(&cur[d.y], 1);
        int p2 = atomicAdd(&cur[d.z], 1);
        int p3 = atomicAdd(&cur[d.w], 1);
        csr[p0] = u.x; csr[p1] = u.y; csr[p2] = u.z; csr[p3] = u.w;
    } else {
        for (; i < E; i++) {
            int p = atomicAdd(&cur[dst[i]], 1);
            csr[p] = src[i];
        }
    }
}

// ---------------- gather aggregation: LPN lanes per dst node ----------------
// (R7 version: H=2 -> 2 nodes/warp; H=1 -> 4 nodes/warp; unroll-4)
template <int H, int F, bool RELU>
__global__ void node_kernel(const int* __restrict__ ptr,
                            const int* __restrict__ csr,
                            const __half* __restrict__ feath,
                            const float* __restrict__ t,
                            const float* __restrict__ bias,
                            float* __restrict__ out, int N) {
    constexpr int LPN = H * F / 8;            // 16 (H=2) or 8 (H=1)
    int gid  = blockIdx.x * blockDim.x + threadIdx.x;
    int node = gid / LPN;
    int lane = gid % LPN;
    if (node >= N) return;
    const int beg = ptr[node];
    const int end = ptr[node + 1];
    const int h   = (H == 2) ? (lane >> 3) : 0;

    const uint4* feat8 = (const uint4*)feath;

    float acc[8];
#pragma unroll
    for (int k = 0; k < 8; k++) acc[k] = 0.f;
    float d = 0.f;

    int i = beg;
    for (; i + 4 <= end; i += 4) {
        int u0 = __ldg(&csr[i + 0]);
        int u1 = __ldg(&csr[i + 1]);
        int u2 = __ldg(&csr[i + 2]);
        int u3 = __ldg(&csr[i + 3]);
        float t0 = __ldg(&t[(size_t)u0 * H + h]);
        float t1 = __ldg(&t[(size_t)u1 * H + h]);
        float t2 = __ldg(&t[(size_t)u2 * H + h]);
        float t3 = __ldg(&t[(size_t)u3 * H + h]);
        uint4 v0 = feat8[(size_t)u0 * LPN + lane];
        uint4 v1 = feat8[(size_t)u1 * LPN + lane];
        uint4 v2 = feat8[(size_t)u2 * LPN + lane];
        uint4 v3 = feat8[(size_t)u3 * LPN + lane];
        d += (t0 + t1) + (t2 + t3);
        const __half2* p0 = (const __half2*)&v0;
        const __half2* p1 = (const __half2*)&v1;
        const __half2* p2 = (const __half2*)&v2;
        const __half2* p3 = (const __half2*)&v3;
#pragma unroll
        for (int k = 0; k < 4; k++) {
            float2 f0 = __half22float2(p0[k]);
            float2 f1 = __half22float2(p1[k]);
            float2 f2 = __half22float2(p2[k]);
            float2 f3 = __half22float2(p3[k]);
            acc[2*k]   = fmaf(t0, f0.x, acc[2*k]);
            acc[2*k+1] = fmaf(t0, f0.y, acc[2*k+1]);
            acc[2*k]   = fmaf(t1, f1.x, acc[2*k]);
            acc[2*k+1] = fmaf(t1, f1.y, acc[2*k+1]);
            acc[2*k]   = fmaf(t2, f2.x, acc[2*k]);
            acc[2*k+1] = fmaf(t2, f2.y, acc[2*k+1]);
            acc[2*k]   = fmaf(t3, f3.x, acc[2*k]);
            acc[2*k+1] = fmaf(t3, f3.y, acc[2*k+1]);
        }
    }
    for (; i < end; i++) {
        int u = __ldg(&csr[i]);
        float tv = __ldg(&t[(size_t)u * H + h]);
        uint4 v = feat8[(size_t)u * LPN + lane];
        const __half2* p = (const __half2*)&v;
        d += tv;
#pragma unroll
        for (int k = 0; k < 4; k++) {
            float2 f = __half22float2(p[k]);
            acc[2*k]   = fmaf(tv, f.x, acc[2*k]);
            acc[2*k+1] = fmaf(tv, f.y, acc[2*k+1]);
        }
    }

    float inv = d > 0.f ? __frcp_rn(d) : 0.f;
    float4 b0 = ((const float4*)bias)[lane * 2 + 0];
    float4 b1 = ((const float4*)bias)[lane * 2 + 1];
    float4 o0, o1;
    o0.x = fmaf(acc[0], inv, b0.x); o0.y = fmaf(acc[1], inv, b0.y);
    o0.z = fmaf(acc[2], inv, b0.z); o0.w = fmaf(acc[3], inv, b0.w);
    o1.x = fmaf(acc[4], inv, b1.x); o1.y = fmaf(acc[5], inv, b1.y);
    o1.z = fmaf(acc[6], inv, b1.z); o1.w = fmaf(acc[7], inv, b1.w);
    if (RELU) {
        o0.x = fmaxf(o0.x, 0.f); o0.y = fmaxf(o0.y, 0.f);
        o0.z = fmaxf(o0.z, 0.f); o0.w = fmaxf(o0.w, 0.f);
        o1.x = fmaxf(o1.x, 0.f); o1.y = fmaxf(o1.y, 0.f);
        o1.z = fmaxf(o1.z, 0.f); o1.w = fmaxf(o1.w, 0.f);
    }
    ((float4*)out)[(size_t)node * LPN * 2 + lane * 2 + 0] = o0;
    ((float4*)out)[(size_t)node * LPN * 2 + lane * 2 + 1] = o1;
}

// ---------------------------------------------------------------------------
static cudaStream_t s_side = nullptr;
static cudaEvent_t  ev_fork = nullptr, ev_join = nullptr;

extern "C" void kernel_launch(void* const* d_in, const int* in_sizes, int n_in,
                              void* d_out, int out_size) {
    const float* feat    = (const float*)d_in[0];
    const float* W0      = (const float*)d_in[1];
    const float* attn_l0 = (const float*)d_in[2];
    const float* bias0   = (const float*)d_in[3];
    const float* W1      = (const float*)d_in[4];
    const float* attn_l1 = (const float*)d_in[5];
    const float* bias1   = (const float*)d_in[6];
    const float* W2      = (const float*)d_in[7];
    const float* attn_l2 = (const float*)d_in[8];
    const float* bias2   = (const float*)d_in[9];
    const int*   src     = (const int*)d_in[10];
    const int*   dst     = (const int*)d_in[11];

    const int N = in_sizes[0] / 128;
    const int E = in_sizes[10];

    __half* p_feath;
    float *p_hid, *p_t;
    int *p_cnt, *p_ptr, *p_cur, *p_csr;
    cudaGetSymbolAddress((void**)&p_feath, g_feat_h);
    cudaGetSymbolAddress((void**)&p_hid,   g_hid);
    cudaGetSymbolAddress((void**)&p_t,     g_t);
    cudaGetSymbolAddress((void**)&p_cnt,   g_cnt);
    cudaGetSymbolAddress((void**)&p_ptr,   g_ptr);
    cudaGetSymbolAddress((void**)&p_cur,   g_cur);
    cudaGetSymbolAddress((void**)&p_csr,   g_csr);

    if (s_side == nullptr) {
        cudaStreamCreateWithFlags(&s_side, cudaStreamNonBlocking);
        cudaEventCreateWithFlags(&ev_fork, cudaEventDisableTiming);
        cudaEventCreateWithFlags(&ev_join, cudaEventDisableTiming);
    }

    constexpr int SK = 128 + 8;
    const int SMEM128 = (2 * 128 + 2 * 128) * SK * 2 + 128 * 2 * 4;
    const int SMEM64  = (2 * 128 + 2 * 64)  * SK * 2 + 128 * 1 * 4;
    cudaFuncSetAttribute(gemm_tc_kernel<128, 2>,
                         cudaFuncAttributeMaxDynamicSharedMemorySize, SMEM128);
    cudaFuncSetAttribute(gemm_tc_kernel<64, 1>,
                         cudaFuncAttributeMaxDynamicSharedMemorySize, SMEM64);

    const int gGemm   = (N + 127) / 128;
    const int gEdge4  = (E / 4 + 255) / 256 + 1;
    const int gNode16 = (N * 16 + 255) / 256;
    const int gNode8  = (N * 8 + 255) / 256;

    // -------- fork: CSR build on side stream, GEMM0 on main --------
    // Launch order chosen so the profiler's fixed capture slot lands on
    // gemm_tc_kernel instead of scatter (dataflow unchanged).
    cudaEventRecord(ev_fork, 0);
    cudaStreamWaitEvent(s_side, ev_fork, 0);

    zero_cnt_kernel<<<(N + 1 + 255) / 256, 256, 0, s_side>>>(p_cnt, N + 1);
    hist_kernel<<<gEdge4, 256, 0, s_side>>>(dst, p_cnt, E);
    scan_kernel<<<1, 1024, 0, s_side>>>(p_cnt, p_ptr, p_cur, N);

    gemm_tc_kernel<128, 2><<<gGemm, 256, SMEM128>>>(feat, W0, attn_l0, p_feath, p_t, N);

    scatter_kernel<<<gEdge4, 256, 0, s_side>>>(src, dst, p_cur, p_csr, E);
    cudaEventRecord(ev_join, s_side);

    cudaStreamWaitEvent(0, ev_join, 0);

    node_kernel<2, 64, true><<<gNode16, 256>>>(p_ptr, p_csr, p_feath, p_t, bias0, p_hid, N);

    gemm_tc_kernel<128, 2><<<gGemm, 256, SMEM128>>>(p_hid, W1, attn_l1, p_feath, p_t, N);
    node_kernel<2, 64, true><<<gNode16, 256>>>(p_ptr, p_csr, p_feath, p_t, bias1, p_hid, N);

    gemm_tc_kernel<64, 1><<<gGemm, 256, SMEM64>>>(p_hid, W2, attn_l2, p_feath, p_t, N);
    node_kernel<1, 64, false><<<gNode8, 256>>>(p_ptr, p_csr, p_feath, p_t, bias2, (float*)d_out, N);
}

// round 10
// speedup vs baseline: 1.1329x; 1.0922x over previous
#include <cuda_runtime.h>
#include <cuda_fp16.h>
#include <cstdint>

// ---------------------------------------------------------------------------
// GAT 3-layer forward, gather-based (CSR by dst).
// R10: TC GEMM widened to 512 threads / 16 warps per block (warp tile 32x32)
// to fix the 12.5%-occupancy latency starvation seen in the R9 profile.
// 3-pass hi/lo fp16 mma, fused score epilogue, CSR overlapped with GEMM0.
// ---------------------------------------------------------------------------

#define MAXN 50000
#define MAXE 800000
#define MAXW 128

__device__ __half g_feat_h[MAXN * MAXW];
__device__ float  g_hid [MAXN * MAXW];
__device__ float  g_t   [MAXN * 2];
__device__ int g_cnt[MAXN + 1];
__device__ int g_ptr[MAXN + 1];
__device__ int g_cur[MAXN + 1];
__device__ int g_csr[MAXE];

__device__ __forceinline__ void mma16816(float* d, const uint32_t* a, const uint32_t* b) {
    asm volatile(
        "mma.sync.aligned.m16n8k16.row.col.f32.f16.f16.f32 "
        "{%0,%1,%2,%3}, {%4,%5,%6,%7}, {%8,%9}, {%0,%1,%2,%3};\n"
        : "+f"(d[0]), "+f"(d[1]), "+f"(d[2]), "+f"(d[3])
        : "r"(a[0]), "r"(a[1]), "r"(a[2]), "r"(a[3]), "r"(b[0]), "r"(b[1]));
}

// ---------------- tensor-core GEMM + fused score epilogue ----------------
// 512 threads, warp grid 4x4, warp tile 32 x WN (WN = BN/4).
template <int BN, int H>
__global__ void __launch_bounds__(512, 1)
gemm_tc_kernel(const float* __restrict__ A,
               const float* __restrict__ W,
               const float* __restrict__ attn,
               __half* __restrict__ C_h,
               float* __restrict__ t, int N) {
    constexpr int BM = 128, K = 128;
    constexpr int SK = K + 8;
    constexpr int WN = BN / 4;         // 32 (BN=128) or 16 (BN=64)
    constexpr int MT = 2;              // m16 tiles per warp (warp M = 32)
    constexpr int NT = WN / 8;         // 4 or 2
    constexpr int F  = BN / H;
    constexpr int THREADS = 512;

    extern __shared__ __half sm[];
    __half* sAhi = sm;
    __half* sAlo = sAhi + BM * SK;
    __half* sWhi = sAlo + BM * SK;
    __half* sWlo = sWhi + BN * SK;
    float*  sm_el = (float*)(sWlo + BN * SK);

    const int tid  = threadIdx.x;
    const int warp = tid >> 5;
    const int lane = tid & 31;
    const int row0 = blockIdx.x * BM;
    const int m0w  = (warp >> 2) * 32;
    const int n0w  = (warp & 3) * WN;
    const int fr   = lane >> 2;
    const int fc   = lane & 3;

    for (int i = tid; i < BM * H; i += THREADS) sm_el[i] = 0.f;

    const float4* A4 = (const float4*)A;
    for (int f = tid; f < BM * 32; f += THREADS) {
        int r = f >> 5, c4 = f & 31;
        float4 v = make_float4(0.f, 0.f, 0.f, 0.f);
        if (row0 + r < N) v = A4[(size_t)(row0 + r) * 32 + c4];
        float vv[4] = {v.x, v.y, v.z, v.w};
        __half hi[4], lo[4];
#pragma unroll
        for (int j = 0; j < 4; j++) {
            hi[j] = __float2half(vv[j]);
            lo[j] = __float2half(vv[j] - __half2float(hi[j]));
        }
        int off = r * SK + c4 * 4;
        *(uint2*)&sAhi[off] = *(uint2*)hi;
        *(uint2*)&sAlo[off] = *(uint2*)lo;
    }
    const float4* W4 = (const float4*)W;
    for (int f = tid; f < BN * 32; f += THREADS) {
        int n = f >> 5, c4 = f & 31;
        float4 v = W4[(size_t)n * 32 + c4];
        float vv[4] = {v.x, v.y, v.z, v.w};
        __half hi[4], lo[4];
#pragma unroll
        for (int j = 0; j < 4; j++) {
            hi[j] = __float2half(vv[j]);
            lo[j] = __float2half(vv[j] - __half2float(hi[j]));
        }
        int off = n * SK + c4 * 4;
        *(uint2*)&sWhi[off] = *(uint2*)hi;
        *(uint2*)&sWlo[off] = *(uint2*)lo;
    }
    __syncthreads();

    float acc[MT][NT][4];
#pragma unroll
    for (int mt = 0; mt < MT; mt++)
#pragma unroll
        for (int nt = 0; nt < NT; nt++)
#pragma unroll
            for (int j = 0; j < 4; j++) acc[mt][nt][j] = 0.f;

#pragma unroll
    for (int kt = 0; kt < 8; kt++) {
        const int k0 = kt * 16;
        uint32_t ahi[MT][4], alo[MT][4];
#pragma unroll
        for (int mt = 0; mt < MT; mt++) {
            const __half* pa = &sAhi[(m0w + mt * 16 + fr) * SK + k0 + fc * 2];
            const __half* pl = &sAlo[(m0w + mt * 16 + fr) * SK + k0 + fc * 2];
            ahi[mt][0] = *(const uint32_t*)pa;
            ahi[mt][1] = *(const uint32_t*)(pa + 8 * SK);
            ahi[mt][2] = *(const uint32_t*)(pa + 8);
            ahi[mt][3] = *(const uint32_t*)(pa + 8 * SK + 8);
            alo[mt][0] = *(const uint32_t*)pl;
            alo[mt][1] = *(const uint32_t*)(pl + 8 * SK);
            alo[mt][2] = *(const uint32_t*)(pl + 8);
            alo[mt][3] = *(const uint32_t*)(pl + 8 * SK + 8);
        }
        uint32_t bhi[NT][2], blo[NT][2];
#pragma unroll
        for (int nt = 0; nt < NT; nt++) {
            const __half* pb = &sWhi[(n0w + nt * 8 + fr) * SK + k0 + fc * 2];
            const __half* pl = &sWlo[(n0w + nt * 8 + fr) * SK + k0 + fc * 2];
            bhi[nt][0] = *(const uint32_t*)pb;
            bhi[nt][1] = *(const uint32_t*)(pb + 8);
            blo[nt][0] = *(const uint32_t*)pl;
            blo[nt][1] = *(const uint32_t*)(pl + 8);
        }
#pragma unroll
        for (int mt = 0; mt < MT; mt++)
#pragma unroll
            for (int nt = 0; nt < NT; nt++) {
                mma16816(acc[mt][nt], ahi[mt], bhi[nt]);
                mma16816(acc[mt][nt], ahi[mt], blo[nt]);
                mma16816(acc[mt][nt], alo[mt], bhi[nt]);
            }
    }

    const int hh = n0w / F;
    float av0[NT], av1[NT];
#pragma unroll
    for (int nt = 0; nt < NT; nt++) {
        int col = n0w + nt * 8 + fc * 2;
        av0[nt] = attn[col];
        av1[nt] = attn[col + 1];
    }
#pragma unroll
    for (int mt = 0; mt < MT; mt++) {
        int rb0 = m0w + mt * 16 + fr;
        int rb1 = rb0 + 8;
        float p0 = 0.f, p1 = 0.f;
#pragma unroll
        for (int nt = 0; nt < NT; nt++) {
            p0 += acc[mt][nt][0] * av0[nt] + acc[mt][nt][1] * av1[nt];
            p1 += acc[mt][nt][2] * av0[nt] + acc[mt][nt][3] * av1[nt];
        }
        atomicAdd(&sm_el[rb0 * H + hh], p0);
        atomicAdd(&sm_el[rb1 * H + hh], p1);
        int g0 = row0 + rb0, g1 = row0 + rb1;
        if (g0 < N) {
#pragma unroll
            for (int nt = 0; nt < NT; nt++) {
                int col = n0w + nt * 8 + fc * 2;
                __half2 hv = __halves2half2(__float2half(acc[mt][nt][0]),
                                            __float2half(acc[mt][nt][1]));
                *(__half2*)&C_h[(size_t)g0 * BN + col] = hv;
            }
        }
        if (g1 < N) {
#pragma unroll
            for (int nt = 0; nt < NT; nt++) {
                int col = n0w + nt * 8 + fc * 2;
                __half2 hv = __halves2half2(__float2half(acc[mt][nt][2]),
                                            __float2half(acc[mt][nt][3]));
                *(__half2*)&C_h[(size_t)g1 * BN + col] = hv;
            }
        }
    }
    __syncthreads();
    for (int i = tid; i < BM * H; i += THREADS) {
        int r = i / H, h2 = i % H;
        int row = row0 + r;
        if (row < N) {
            float el = sm_el[i];
            float sv = el > 0.f ? el : 0.2f * el;
            t[(size_t)row * H + h2] = __expf(sv);
        }
    }
}

// ---------------- CSR build ----------------
__global__ void zero_cnt_kernel(int* __restrict__ cnt, int n) {
    int i = blockIdx.x * blockDim.x + threadIdx.x;
    if (i < n) cnt[i] = 0;
}

__global__ void hist_kernel(const int* __restrict__ dst, int* __restrict__ cnt, int E) {
    int i = (blockIdx.x * blockDim.x + threadIdx.x) * 4;
    if (i + 4 <= E) {
        int4 d = *(const int4*)&dst[i];
        atomicAdd(&cnt[d.x], 1);
        atomicAdd(&cnt[d.y], 1);
        atomicAdd(&cnt[d.z], 1);
        atomicAdd(&cnt[d.w], 1);
    } else {
        for (; i < E; i++) atomicAdd(&cnt[dst[i]], 1);
    }
}

__global__ void scan_kernel(const int* __restrict__ cnt, int* __restrict__ ptr,
                            int* __restrict__ cur, int N) {
    __shared__ int part[1024];
    const int tid = threadIdx.x;
    const int chunk = (N + 1023) / 1024;
    const int b = tid * chunk;
    int s = 0;
    for (int i = 0; i < chunk; i++)
        if (b + i < N) s += cnt[b + i];
    part[tid] = s;
    __syncthreads();
    for (int off = 1; off < 1024; off <<= 1) {
        int v = (tid >= off) ? part[tid - off] : 0;
        __syncthreads();
        part[tid] += v;
        __syncthreads();
    }
    int run = (tid > 0) ? part[tid - 1] : 0;
    for (int i = 0; i < chunk; i++) {
        if (b + i < N) {
            ptr[b + i] = run;
            cur[b + i] = run;
            run += cnt[b + i];
        }
    }
    if (tid == 1023) ptr[N] = part[1023];
}

__global__ void scatter_kernel(const int* __restrict__ src, const int* __restrict__ dst,
                               int* __restrict__ cur, int* __restrict__ csr, int E) {
    int i = (blockIdx.x * blockDim.x + threadIdx.x) * 4;
    if (i + 4 <= E) {
        int4 d = *(const int4*)&dst[i];
        int4 u = *(const int4*)&src[i];
        int p0 = atomicAdd(&cur[d.x], 1);
        int p1 = atomicAdd(&cur[d.y], 1);
        int p2 = atomicAdd(&cur[d.z], 1);
        int p3 = atomicAdd(&cur[d.w], 1);
        csr[p0] = u.x; csr[p1] = u.y; csr[p2] = u.z; csr[p3] = u.w;
    } else {
        for (; i < E; i++) {
            int p = atomicAdd(&cur[dst[i]], 1);
            csr[p] = src[i];
        }
    }
}

// ---------------- gather aggregation: LPN lanes per dst node ----------------
template <int H, int F, bool RELU>
__global__ void node_kernel(const int* __restrict__ ptr,
                            const int* __restrict__ csr,
                            const __half* __restrict__ feath,
                            const float* __restrict__ t,
                            const float* __restrict__ bias,
                            float* __restrict__ out, int N) {
    constexpr int LPN = H * F / 8;            // 16 (H=2) or 8 (H=1)
    int gid  = blockIdx.x * blockDim.x + threadIdx.x;
    int node = gid / LPN;
    int lane = gid % LPN;
    if (node >= N) return;
    const int beg = ptr[node];
    const int end = ptr[node + 1];
    const int h   = (H == 2) ? (lane >> 3) : 0;

    const uint4* feat8 = (const uint4*)feath;

    float acc[8];
#pragma unroll
    for (int k = 0; k < 8; k++) acc[k] = 0.f;
    float d = 0.f;

    int i = beg;
    for (; i + 4 <= end; i += 4) {
        int u0 = __ldg(&csr[i + 0]);
        int u1 = __ldg(&csr[i + 1]);
        int u2 = __ldg(&csr[i + 2]);
        int u3 = __ldg(&csr[i + 3]);
        float t0 = __ldg(&t[(size_t)u0 * H + h]);
        float t1 = __ldg(&t[(size_t)u1 * H + h]);
        float t2 = __ldg(&t[(size_t)u2 * H + h]);
        float t3 = __ldg(&t[(size_t)u3 * H + h]);
        uint4 v0 = feat8[(size_t)u0 * LPN + lane];
        uint4 v1 = feat8[(size_t)u1 * LPN + lane];
        uint4 v2 = feat8[(size_t)u2 * LPN + lane];
        uint4 v3 = feat8[(size_t)u3 * LPN + lane];
        d += (t0 + t1) + (t2 + t3);
        const __half2* p0 = (const __half2*)&v0;
        const __half2* p1 = (const __half2*)&v1;
        const __half2* p2 = (const __half2*)&v2;
        const __half2* p3 = (const __half2*)&v3;
#pragma unroll
        for (int k = 0; k < 4; k++) {
            float2 f0 = __half22float2(p0[k]);
            float2 f1 = __half22float2(p1[k]);
            float2 f2 = __half22float2(p2[k]);
            float2 f3 = __half22float2(p3[k]);
            acc[2*k]   = fmaf(t0, f0.x, acc[2*k]);
            acc[2*k+1] = fmaf(t0, f0.y, acc[2*k+1]);
            acc[2*k]   = fmaf(t1, f1.x, acc[2*k]);
            acc[2*k+1] = fmaf(t1, f1.y, acc[2*k+1]);
            acc[2*k]   = fmaf(t2, f2.x, acc[2*k]);
            acc[2*k+1] = fmaf(t2, f2.y, acc[2*k+1]);
            acc[2*k]   = fmaf(t3, f3.x, acc[2*k]);
            acc[2*k+1] = fmaf(t3, f3.y, acc[2*k+1]);
        }
    }
    for (; i < end; i++) {
        int u = __ldg(&csr[i]);
        float tv = __ldg(&t[(size_t)u * H + h]);
        uint4 v = feat8[(size_t)u * LPN + lane];
        const __half2* p = (const __half2*)&v;
        d += tv;
#pragma unroll
        for (int k = 0; k < 4; k++) {
            float2 f = __half22float2(p[k]);
            acc[2*k]   = fmaf(tv, f.x, acc[2*k]);
            acc[2*k+1] = fmaf(tv, f.y, acc[2*k+1]);
        }
    }

    float inv = d > 0.f ? __frcp_rn(d) : 0.f;
    float4 b0 = ((const float4*)bias)[lane * 2 + 0];
    float4 b1 = ((const float4*)bias)[lane * 2 + 1];
    float4 o0, o1;
    o0.x = fmaf(acc[0], inv, b0.x); o0.y = fmaf(acc[1], inv, b0.y);
    o0.z = fmaf(acc[2], inv, b0.z); o0.w = fmaf(acc[3], inv, b0.w);
    o1.x = fmaf(acc[4], inv, b1.x); o1.y = fmaf(acc[5], inv, b1.y);
    o1.z = fmaf(acc[6], inv, b1.z); o1.w = fmaf(acc[7], inv, b1.w);
    if (RELU) {
        o0.x = fmaxf(o0.x, 0.f); o0.y = fmaxf(o0.y, 0.f);
        o0.z = fmaxf(o0.z, 0.f); o0.w = fmaxf(o0.w, 0.f);
        o1.x = fmaxf(o1.x, 0.f); o1.y = fmaxf(o1.y, 0.f);
        o1.z = fmaxf(o1.z, 0.f); o1.w = fmaxf(o1.w, 0.f);
    }
    ((float4*)out)[(size_t)node * LPN * 2 + lane * 2 + 0] = o0;
    ((float4*)out)[(size_t)node * LPN * 2 + lane * 2 + 1] = o1;
}

// ---------------------------------------------------------------------------
static cudaStream_t s_side = nullptr;
static cudaEvent_t  ev_fork = nullptr, ev_join = nullptr;

extern "C" void kernel_launch(void* const* d_in, const int* in_sizes, int n_in,
                              void* d_out, int out_size) {
    const float* feat    = (const float*)d_in[0];
    const float* W0      = (const float*)d_in[1];
    const float* attn_l0 = (const float*)d_in[2];
    const float* bias0   = (const float*)d_in[3];
    const float* W1      = (const float*)d_in[4];
    const float* attn_l1 = (const float*)d_in[5];
    const float* bias1   = (const float*)d_in[6];
    const float* W2      = (const float*)d_in[7];
    const float* attn_l2 = (const float*)d_in[8];
    const float* bias2   = (const float*)d_in[9];
    const int*   src     = (const int*)d_in[10];
    const int*   dst     = (const int*)d_in[11];

    const int N = in_sizes[0] / 128;
    const int E = in_sizes[10];

    __half* p_feath;
    float *p_hid, *p_t;
    int *p_cnt, *p_ptr, *p_cur, *p_csr;
    cudaGetSymbolAddress((void**)&p_feath, g_feat_h);
    cudaGetSymbolAddress((void**)&p_hid,   g_hid);
    cudaGetSymbolAddress((void**)&p_t,     g_t);
    cudaGetSymbolAddress((void**)&p_cnt,   g_cnt);
    cudaGetSymbolAddress((void**)&p_ptr,   g_ptr);
    cudaGetSymbolAddress((void**)&p_cur,   g_cur);
    cudaGetSymbolAddress((void**)&p_csr,   g_csr);

    if (s_side == nullptr) {
        cudaStreamCreateWithFlags(&s_side, cudaStreamNonBlocking);
        cudaEventCreateWithFlags(&ev_fork, cudaEventDisableTiming);
        cudaEventCreateWithFlags(&ev_join, cudaEventDisableTiming);
    }

    constexpr int SK = 128 + 8;
    const int SMEM128 = (2 * 128 + 2 * 128) * SK * 2 + 128 * 2 * 4;
    const int SMEM64  = (2 * 128 + 2 * 64)  * SK * 2 + 128 * 1 * 4;
    cudaFuncSetAttribute(gemm_tc_kernel<128, 2>,
                         cudaFuncAttributeMaxDynamicSharedMemorySize, SMEM128);
    cudaFuncSetAttribute(gemm_tc_kernel<64, 1>,
                         cudaFuncAttributeMaxDynamicSharedMemorySize, SMEM64);

    const int gGemm   = (N + 127) / 128;
    const int gEdge4  = (E / 4 + 255) / 256 + 1;
    const int gNode16 = (N * 16 + 255) / 256;
    const int gNode8  = (N * 8 + 255) / 256;

    // -------- fork: CSR build on side stream, GEMM0 on main --------
    cudaEventRecord(ev_fork, 0);
    cudaStreamWaitEvent(s_side, ev_fork, 0);

    zero_cnt_kernel<<<(N + 1 + 255) / 256, 256, 0, s_side>>>(p_cnt, N + 1);
    hist_kernel<<<gEdge4, 256, 0, s_side>>>(dst, p_cnt, E);
    scan_kernel<<<1, 1024, 0, s_side>>>(p_cnt, p_ptr, p_cur, N);

    gemm_tc_kernel<128, 2><<<gGemm, 512, SMEM128>>>(feat, W0, attn_l0, p_feath, p_t, N);

    scatter_kernel<<<gEdge4, 256, 0, s_side>>>(src, dst, p_cur, p_csr, E);
    cudaEventRecord(ev_join, s_side);

    cudaStreamWaitEvent(0, ev_join, 0);

    node_kernel<2, 64, true><<<gNode16, 256>>>(p_ptr, p_csr, p_feath, p_t, bias0, p_hid, N);

    gemm_tc_kernel<128, 2><<<gGemm, 512, SMEM128>>>(p_hid, W1, attn_l1, p_feath, p_t, N);
    node_kernel<2, 64, true><<<gNode16, 256>>>(p_ptr, p_csr, p_feath, p_t, bias1, p_hid, N);

    gemm_tc_kernel<64, 1><<<gGemm, 512, SMEM64>>>(p_hid, W2, attn_l2, p_feath, p_t, N);
    node_kernel<1, 64, false><<<gNode8, 256>>>(p_ptr, p_csr, p_feath, p_t, bias2, (float*)d_out, N);
}